// round 1
// baseline (speedup 1.0000x reference)
#include <cuda_runtime.h>
#include <math.h>

#define Bsz 64
#define Tt  256
#define Ff  512
#define Hh  1024
#define Oo  512
#define G3  3072   // 3*Hh

// Output layout: outputs [T,B,O] | num_selections (1) | sel_weights [T,B,F]
#define NSEL_OFF  (Tt*Bsz*Oo)
#define SELW_OFF  (Tt*Bsz*Oo + 1)

// Scratch (device globals: no allocation allowed)
__device__ float g_h[Bsz*Hh];        // hidden state
__device__ float g_currin[Bsz*Ff];   // masked input for current step
__device__ float g_gi[Bsz*G3];       // curr_in @ W_ih^T
__device__ float g_gh[Bsz*G3];       // h @ W_hh^T
__device__ int   g_nsel;             // integer selection count (exact, deterministic)

// ---------------------------------------------------------------------------
__global__ void __launch_bounds__(256) k_init(const float* __restrict__ x,
                                              float* __restrict__ out) {
    int idx = blockIdx.x * 256 + threadIdx.x;   // grid covers Bsz*Hh = 65536
    if (idx < Bsz*Hh) g_h[idx] = 0.f;
    if (idx < Bsz*Ff) {
        int b = idx >> 9;                        // f = idx & 511
        int f = idx & 511;
        g_currin[idx] = x[b*(Tt*Ff) + f];        // x[b,0,f]
        out[SELW_OFF + idx] = 1.0f;              // sel_weights[0,b,f] = 1
    }
    if (idx == 0) g_nsel = 0;
}

// ---------------------------------------------------------------------------
// K1: gi = curr_in @ W_ih^T  (blocks 0..95,  K=512)
//     gh = h       @ W_hh^T  (blocks 96..191, K=1024)
// C tile: 64(M) x 32(N), 256 threads, micro 4x2.
__global__ void __launch_bounds__(256) k_gates(const float* __restrict__ Wih,
                                               const float* __restrict__ Whh) {
    __shared__ float As[32][68];   // [k][m], padded for conflict-light transpose store
    __shared__ float Ws[32][36];   // [k][n]

    int bid = blockIdx.x;
    const float* A; const float* W; float* C; int K; int n0;
    if (bid < 96) { A = g_currin; W = Wih; C = g_gi; K = Ff; n0 = bid * 32; }
    else          { A = g_h;      W = Whh; C = g_gh; K = Hh; n0 = (bid - 96) * 32; }

    int tid = threadIdx.x;
    int tn = tid & 15;          // n pair index (0..15) -> cols tn*2, tn*2+1
    int tm = tid >> 4;          // m group (0..15)      -> rows tm*4..tm*4+3
    int am = tid >> 2;          // loader: A row 0..63
    int ak = (tid & 3) << 3;    // loader: A k-offset {0,8,16,24}
    int wn = tid >> 3;          // loader: W row 0..31
    int wk = (tid & 7) << 2;    // loader: W k-offset {0,4,...,28}

    const float* arow = A + am * K;
    const float* wrow = W + (size_t)(n0 + wn) * K;

    float acc00=0,acc01=0,acc10=0,acc11=0,acc20=0,acc21=0,acc30=0,acc31=0;

    for (int k0 = 0; k0 < K; k0 += 32) {
        float4 a0 = *(const float4*)&arow[k0 + ak];
        float4 a1 = *(const float4*)&arow[k0 + ak + 4];
        float4 w0 = *(const float4*)&wrow[k0 + wk];
        __syncthreads();
        As[ak+0][am]=a0.x; As[ak+1][am]=a0.y; As[ak+2][am]=a0.z; As[ak+3][am]=a0.w;
        As[ak+4][am]=a1.x; As[ak+5][am]=a1.y; As[ak+6][am]=a1.z; As[ak+7][am]=a1.w;
        Ws[wk+0][wn]=w0.x; Ws[wk+1][wn]=w0.y; Ws[wk+2][wn]=w0.z; Ws[wk+3][wn]=w0.w;
        __syncthreads();
        #pragma unroll
        for (int k = 0; k < 32; k++) {
            float4 a = *(const float4*)&As[k][tm << 2];
            float w0_ = Ws[k][tn*2], w1_ = Ws[k][tn*2+1];
            acc00 += a.x*w0_; acc01 += a.x*w1_;
            acc10 += a.y*w0_; acc11 += a.y*w1_;
            acc20 += a.z*w0_; acc21 += a.z*w1_;
            acc30 += a.w*w0_; acc31 += a.w*w1_;
        }
    }

    int m = tm << 2;
    int n = n0 + tn * 2;
    *(float2*)&C[(m+0)*G3 + n] = make_float2(acc00, acc01);
    *(float2*)&C[(m+1)*G3 + n] = make_float2(acc10, acc11);
    *(float2*)&C[(m+2)*G3 + n] = make_float2(acc20, acc21);
    *(float2*)&C[(m+3)*G3 + n] = make_float2(acc30, acc31);
}

// ---------------------------------------------------------------------------
// K2: GRU gate nonlinearity + h update (64x1024 elementwise)
__global__ void __launch_bounds__(256) k_update(const float* __restrict__ bih,
                                                const float* __restrict__ bhh) {
    int idx = blockIdx.x * 256 + threadIdx.x;   // 65536 threads
    int b = idx >> 10;
    int j = idx & 1023;
    const float* gi = g_gi + b * G3;
    const float* gh = g_gh + b * G3;
    float ir = gi[j]        + bih[j],        hr = gh[j]        + bhh[j];
    float iz = gi[Hh + j]   + bih[Hh + j],   hz = gh[Hh + j]   + bhh[Hh + j];
    float in_= gi[2*Hh + j] + bih[2*Hh + j], hn = gh[2*Hh + j] + bhh[2*Hh + j];
    float r = 1.f / (1.f + expf(-(ir + hr)));
    float z = 1.f / (1.f + expf(-(iz + hz)));
    float nn = tanhf(in_ + r * hn);
    float h = g_h[idx];
    g_h[idx] = (1.f - z) * nn + z * h;
}

// ---------------------------------------------------------------------------
// K3: fused [out | logits] = h @ [W_out^T | W_sel^T]  (C: 64 x 1024)
// Tile 64x16 per block; blocks 0..31 -> out columns, 32..63 -> logits columns.
// Logits epilogue computes the NEXT step's Bernoulli mask, writes
// sel_weights[t+1], g_currin, and accumulates nsel (int atomics).
__global__ void __launch_bounds__(256) k_outsel(
    const float* __restrict__ Wout, const float* __restrict__ bout,
    const float* __restrict__ Wsel, const float* __restrict__ bsel,
    const float* __restrict__ x,    const float* __restrict__ u,
    float* __restrict__ out, int t)
{
    __shared__ float As[32][68];   // [k][m]
    __shared__ float Ws[32][20];   // [k][n]

    int n0 = blockIdx.x * 16;
    bool is_out = (n0 < Oo);
    const float* W = is_out ? Wout : Wsel;
    int nb = is_out ? n0 : (n0 - Oo);

    int tid = threadIdx.x;
    int tn = tid & 15;           // column within tile
    int tm = tid >> 4;           // row group
    int am = tid >> 2;           // A loader row 0..63
    int ak = (tid & 3) << 3;     // A loader k-offset
    int wn = tid >> 4;           // W loader row 0..15
    int wk = (tid & 15) << 1;    // W loader k-offset {0,2,...,30}

    const float* arow = g_h + am * Hh;
    const float* wrow = W + (size_t)(nb + wn) * Hh;

    float acc0=0, acc1=0, acc2=0, acc3=0;

    for (int k0 = 0; k0 < Hh; k0 += 32) {
        float4 a0 = *(const float4*)&arow[k0 + ak];
        float4 a1 = *(const float4*)&arow[k0 + ak + 4];
        float2 w0 = *(const float2*)&wrow[k0 + wk];
        __syncthreads();
        As[ak+0][am]=a0.x; As[ak+1][am]=a0.y; As[ak+2][am]=a0.z; As[ak+3][am]=a0.w;
        As[ak+4][am]=a1.x; As[ak+5][am]=a1.y; As[ak+6][am]=a1.z; As[ak+7][am]=a1.w;
        Ws[wk+0][wn]=w0.x; Ws[wk+1][wn]=w0.y;
        __syncthreads();
        #pragma unroll
        for (int k = 0; k < 32; k++) {
            float4 a = *(const float4*)&As[k][tm << 2];
            float w = Ws[k][tn];
            acc0 += a.x*w; acc1 += a.y*w; acc2 += a.z*w; acc3 += a.w*w;
        }
    }

    int m = tm << 2;
    int n = n0 + tn;
    if (is_out) {
        float bias = bout[n];
        out[(size_t)t*Bsz*Oo + (m+0)*Oo + n] = acc0 + bias;
        out[(size_t)t*Bsz*Oo + (m+1)*Oo + n] = acc1 + bias;
        out[(size_t)t*Bsz*Oo + (m+2)*Oo + n] = acc2 + bias;
        out[(size_t)t*Bsz*Oo + (m+3)*Oo + n] = acc3 + bias;
    } else {
        // Only launched when t < Tt-1 (grid trimmed to 32 blocks on the last step)
        int f = n - Oo;
        float bias = bsel[f];
        float accs[4] = {acc0, acc1, acc2, acc3};
        int cnt = 0;
        #pragma unroll
        for (int i = 0; i < 4; i++) {
            int mb = m + i;
            float logit = accs[i] + bias;
            float sg = 1.f / (1.f + expf(-logit));
            float uu = u[(size_t)(t+1)*Bsz*Ff + mb*Ff + f];
            float w = (sg > uu) ? 1.f : 0.f;
            out[SELW_OFF + (size_t)(t+1)*Bsz*Ff + mb*Ff + f] = w;
            g_currin[mb*Ff + f] = w * x[(size_t)mb*Tt*Ff + (t+1)*Ff + f];
            cnt += (w > 0.5f) ? 1 : 0;
        }
        #pragma unroll
        for (int off = 16; off; off >>= 1)
            cnt += __shfl_down_sync(0xffffffffu, cnt, off);
        if ((tid & 31) == 0 && cnt) atomicAdd(&g_nsel, cnt);
    }
}

// ---------------------------------------------------------------------------
__global__ void k_fin(float* __restrict__ out) {
    if (threadIdx.x == 0) out[NSEL_OFF] = (float)g_nsel;
}

// ---------------------------------------------------------------------------
extern "C" void kernel_launch(void* const* d_in, const int* in_sizes, int n_in,
                              void* d_out, int out_size) {
    const float* x    = (const float*)d_in[0];
    const float* u    = (const float*)d_in[1];
    const float* Wih  = (const float*)d_in[2];
    const float* bih  = (const float*)d_in[3];
    const float* Whh  = (const float*)d_in[4];
    const float* bhh  = (const float*)d_in[5];
    const float* Wout = (const float*)d_in[6];
    const float* bout = (const float*)d_in[7];
    const float* Wsel = (const float*)d_in[8];
    const float* bsel = (const float*)d_in[9];
    float* out = (float*)d_out;

    k_init<<<256, 256>>>(x, out);
    for (int t = 0; t < Tt; t++) {
        k_gates<<<192, 256>>>(Wih, Whh);
        k_update<<<256, 256>>>(bih, bhh);
        int nb = (t < Tt - 1) ? 64 : 32;   // last step: no logits needed
        k_outsel<<<nb, 256>>>(Wout, bout, Wsel, bsel, x, u, out, t);
    }
    k_fin<<<1, 32>>>(out);
}

// round 2
// speedup vs baseline: 1.0173x; 1.0173x over previous
#include <cuda_runtime.h>
#include <math.h>

#define Bsz 64
#define Tt  256
#define Ff  512
#define Hh  1024
#define Oo  512
#define G3  3072   // 3*Hh

// Output layout: outputs [T,B,O] | num_selections (1) | sel_weights [T,B,F]
#define NSEL_OFF  (Tt*Bsz*Oo)
#define SELW_OFF  (Tt*Bsz*Oo + 1)

// Scratch (device globals: no allocation allowed)
__device__ float g_h[Bsz*Hh];        // hidden state
__device__ float g_currin[Bsz*Ff];   // masked input for current step
__device__ float g_gi[Bsz*G3];       // curr_in @ W_ih^T
__device__ float g_gh[Bsz*G3];       // h @ W_hh^T
__device__ int   g_nsel;             // integer selection count (exact, deterministic)

// ---------------------------------------------------------------------------
__global__ void __launch_bounds__(256) k_init(const float* __restrict__ x,
                                              float* __restrict__ out) {
    int idx = blockIdx.x * 256 + threadIdx.x;   // grid covers Bsz*Hh = 65536
    if (idx < Bsz*Hh) g_h[idx] = 0.f;
    if (idx < Bsz*Ff) {
        int b = idx >> 9;                        // f = idx & 511
        int f = idx & 511;
        g_currin[idx] = x[b*(Tt*Ff) + f];        // x[b,0,f]
        out[SELW_OFF + idx] = 1.0f;              // sel_weights[0,b,f] = 1
    }
    if (idx == 0) g_nsel = 0;
}

// ---------------------------------------------------------------------------
// K1: gi = curr_in @ W_ih^T  (blocks 0..95,  K=512)
//     gh = h       @ W_hh^T  (blocks 96..191, K=1024)
// C tile: 64(M) x 32(N), 256 threads, micro 4x2.
__global__ void __launch_bounds__(256) k_gates(const float* __restrict__ Wih,
                                               const float* __restrict__ Whh) {
    __shared__ float As[32][68];   // [k][m], padded for conflict-light transpose store
    __shared__ float Ws[32][36];   // [k][n]

    int bid = blockIdx.x;
    const float* A; const float* W; float* C; int K; int n0;
    if (bid < 96) { A = g_currin; W = Wih; C = g_gi; K = Ff; n0 = bid * 32; }
    else          { A = g_h;      W = Whh; C = g_gh; K = Hh; n0 = (bid - 96) * 32; }

    int tid = threadIdx.x;
    int tn = tid & 15;          // n pair index (0..15) -> cols tn*2, tn*2+1
    int tm = tid >> 4;          // m group (0..15)      -> rows tm*4..tm*4+3
    int am = tid >> 2;          // loader: A row 0..63
    int ak = (tid & 3) << 3;    // loader: A k-offset {0,8,16,24}
    int wn = tid >> 3;          // loader: W row 0..31
    int wk = (tid & 7) << 2;    // loader: W k-offset {0,4,...,28}

    const float* arow = A + am * K;
    const float* wrow = W + (size_t)(n0 + wn) * K;

    float acc00=0,acc01=0,acc10=0,acc11=0,acc20=0,acc21=0,acc30=0,acc31=0;

    for (int k0 = 0; k0 < K; k0 += 32) {
        float4 a0 = *(const float4*)&arow[k0 + ak];
        float4 a1 = *(const float4*)&arow[k0 + ak + 4];
        float4 w0 = *(const float4*)&wrow[k0 + wk];
        __syncthreads();
        As[ak+0][am]=a0.x; As[ak+1][am]=a0.y; As[ak+2][am]=a0.z; As[ak+3][am]=a0.w;
        As[ak+4][am]=a1.x; As[ak+5][am]=a1.y; As[ak+6][am]=a1.z; As[ak+7][am]=a1.w;
        Ws[wk+0][wn]=w0.x; Ws[wk+1][wn]=w0.y; Ws[wk+2][wn]=w0.z; Ws[wk+3][wn]=w0.w;
        __syncthreads();
        #pragma unroll
        for (int k = 0; k < 32; k++) {
            float4 a = *(const float4*)&As[k][tm << 2];
            float w0_ = Ws[k][tn*2], w1_ = Ws[k][tn*2+1];
            acc00 += a.x*w0_; acc01 += a.x*w1_;
            acc10 += a.y*w0_; acc11 += a.y*w1_;
            acc20 += a.z*w0_; acc21 += a.z*w1_;
            acc30 += a.w*w0_; acc31 += a.w*w1_;
        }
    }

    int m = tm << 2;
    int n = n0 + tn * 2;
    *(float2*)&C[(m+0)*G3 + n] = make_float2(acc00, acc01);
    *(float2*)&C[(m+1)*G3 + n] = make_float2(acc10, acc11);
    *(float2*)&C[(m+2)*G3 + n] = make_float2(acc20, acc21);
    *(float2*)&C[(m+3)*G3 + n] = make_float2(acc30, acc31);
}

// ---------------------------------------------------------------------------
// K2: GRU gate nonlinearity + h update (64x1024 elementwise)
__global__ void __launch_bounds__(256) k_update(const float* __restrict__ bih,
                                                const float* __restrict__ bhh) {
    int idx = blockIdx.x * 256 + threadIdx.x;   // 65536 threads
    int b = idx >> 10;
    int j = idx & 1023;
    const float* gi = g_gi + b * G3;
    const float* gh = g_gh + b * G3;
    float ir = gi[j]        + bih[j],        hr = gh[j]        + bhh[j];
    float iz = gi[Hh + j]   + bih[Hh + j],   hz = gh[Hh + j]   + bhh[Hh + j];
    float in_= gi[2*Hh + j] + bih[2*Hh + j], hn = gh[2*Hh + j] + bhh[2*Hh + j];
    float r = 1.f / (1.f + expf(-(ir + hr)));
    float z = 1.f / (1.f + expf(-(iz + hz)));
    float nn = tanhf(in_ + r * hn);
    float h = g_h[idx];
    g_h[idx] = (1.f - z) * nn + z * h;
}

// ---------------------------------------------------------------------------
// K3: fused [out | logits] = h @ [W_out^T | W_sel^T]  (C: 64 x 1024)
// Tile 64x16 per block; blocks 0..31 -> out columns, 32..63 -> logits columns.
// Logits epilogue computes the NEXT step's Bernoulli mask, writes
// sel_weights[t+1], g_currin, and accumulates nsel (int atomics).
__global__ void __launch_bounds__(256) k_outsel(
    const float* __restrict__ Wout, const float* __restrict__ bout,
    const float* __restrict__ Wsel, const float* __restrict__ bsel,
    const float* __restrict__ x,    const float* __restrict__ u,
    float* __restrict__ out, int t)
{
    __shared__ float As[32][68];   // [k][m]
    __shared__ float Ws[32][20];   // [k][n]

    int n0 = blockIdx.x * 16;
    bool is_out = (n0 < Oo);
    const float* W = is_out ? Wout : Wsel;
    int nb = is_out ? n0 : (n0 - Oo);

    int tid = threadIdx.x;
    int tn = tid & 15;           // column within tile
    int tm = tid >> 4;           // row group
    int am = tid >> 2;           // A loader row 0..63
    int ak = (tid & 3) << 3;     // A loader k-offset
    int wn = tid >> 4;           // W loader row 0..15
    int wk = (tid & 15) << 1;    // W loader k-offset {0,2,...,30}

    const float* arow = g_h + am * Hh;
    const float* wrow = W + (size_t)(nb + wn) * Hh;

    float acc0=0, acc1=0, acc2=0, acc3=0;

    for (int k0 = 0; k0 < Hh; k0 += 32) {
        float4 a0 = *(const float4*)&arow[k0 + ak];
        float4 a1 = *(const float4*)&arow[k0 + ak + 4];
        float2 w0 = *(const float2*)&wrow[k0 + wk];
        __syncthreads();
        As[ak+0][am]=a0.x; As[ak+1][am]=a0.y; As[ak+2][am]=a0.z; As[ak+3][am]=a0.w;
        As[ak+4][am]=a1.x; As[ak+5][am]=a1.y; As[ak+6][am]=a1.z; As[ak+7][am]=a1.w;
        Ws[wk+0][wn]=w0.x; Ws[wk+1][wn]=w0.y;
        __syncthreads();
        #pragma unroll
        for (int k = 0; k < 32; k++) {
            float4 a = *(const float4*)&As[k][tm << 2];
            float w = Ws[k][tn];
            acc0 += a.x*w; acc1 += a.y*w; acc2 += a.z*w; acc3 += a.w*w;
        }
    }

    int m = tm << 2;
    int n = n0 + tn;
    if (is_out) {
        float bias = bout[n];
        out[(size_t)t*Bsz*Oo + (m+0)*Oo + n] = acc0 + bias;
        out[(size_t)t*Bsz*Oo + (m+1)*Oo + n] = acc1 + bias;
        out[(size_t)t*Bsz*Oo + (m+2)*Oo + n] = acc2 + bias;
        out[(size_t)t*Bsz*Oo + (m+3)*Oo + n] = acc3 + bias;
    } else {
        // Only launched when t < Tt-1 (grid trimmed to 32 blocks on the last step)
        int f = n - Oo;
        float bias = bsel[f];
        float accs[4] = {acc0, acc1, acc2, acc3};
        int cnt = 0;
        #pragma unroll
        for (int i = 0; i < 4; i++) {
            int mb = m + i;
            float logit = accs[i] + bias;
            float sg = 1.f / (1.f + expf(-logit));
            float uu = u[(size_t)(t+1)*Bsz*Ff + mb*Ff + f];
            float w = (sg > uu) ? 1.f : 0.f;
            out[SELW_OFF + (size_t)(t+1)*Bsz*Ff + mb*Ff + f] = w;
            g_currin[mb*Ff + f] = w * x[(size_t)mb*Tt*Ff + (t+1)*Ff + f];
            cnt += (w > 0.5f) ? 1 : 0;
        }
        #pragma unroll
        for (int off = 16; off; off >>= 1)
            cnt += __shfl_down_sync(0xffffffffu, cnt, off);
        if ((tid & 31) == 0 && cnt) atomicAdd(&g_nsel, cnt);
    }
}

// ---------------------------------------------------------------------------
__global__ void k_fin(float* __restrict__ out) {
    if (threadIdx.x == 0) out[NSEL_OFF] = (float)g_nsel;
}

// ---------------------------------------------------------------------------
extern "C" void kernel_launch(void* const* d_in, const int* in_sizes, int n_in,
                              void* d_out, int out_size) {
    const float* x    = (const float*)d_in[0];
    const float* u    = (const float*)d_in[1];
    const float* Wih  = (const float*)d_in[2];
    const float* bih  = (const float*)d_in[3];
    const float* Whh  = (const float*)d_in[4];
    const float* bhh  = (const float*)d_in[5];
    const float* Wout = (const float*)d_in[6];
    const float* bout = (const float*)d_in[7];
    const float* Wsel = (const float*)d_in[8];
    const float* bsel = (const float*)d_in[9];
    float* out = (float*)d_out;

    k_init<<<256, 256>>>(x, out);
    for (int t = 0; t < Tt; t++) {
        k_gates<<<192, 256>>>(Wih, Whh);
        k_update<<<256, 256>>>(bih, bhh);
        int nb = (t < Tt - 1) ? 64 : 32;   // last step: no logits needed
        k_outsel<<<nb, 256>>>(Wout, bout, Wsel, bsel, x, u, out, t);
    }
    k_fin<<<1, 32>>>(out);
}